// round 1
// baseline (speedup 1.0000x reference)
#include <cuda_runtime.h>
#include <cstdint>
#include <cstdio>

// Problem constants (fixed shapes).
namespace {
constexpr int B_  = 2;
constexpr int H_  = 8;
constexpr int NQ_ = 2048;
constexpr int NK_ = 2048;
constexpr int D_  = 64;
constexpr int HD_ = H_ * D_;        // 512
constexpr int TQ_ = 32;             // q-tile rows per CTA
constexpr int TK_ = 32;             // k-tile rows per iteration
constexpr int ST_ = HD_ + 4;        // smem row stride (floats), pad 4 -> conflict-free
constexpr int SST_ = TK_ + 1;       // S-tile row stride (33)
constexpr int NTHREADS = 256;       // 8 warps = 8 heads

// Shared memory layout (float offsets)
constexpr int OFF_Q = 0;                        // relu(Q) tile  [TQ][ST]
constexpr int OFF_K = OFF_Q + TQ_ * ST_;        // relu(K) tile  [TK][ST]
constexpr int OFF_V = OFF_K + TK_ * ST_;        // V tile        [TK][ST]
constexpr int OFF_S = OFF_V + TK_ * ST_;        // S/P tiles     [H][TQ][SST]
constexpr int SMEM_FLOATS = OFF_S + H_ * TQ_ * SST_;
constexpr size_t SMEM_BYTES = (size_t)SMEM_FLOATS * sizeof(float);  // 231,936 B
}

__device__ __forceinline__ float4 relu4(float4 v) {
    v.x = fmaxf(v.x, 0.f); v.y = fmaxf(v.y, 0.f);
    v.z = fmaxf(v.z, 0.f); v.w = fmaxf(v.w, 0.f);
    return v;
}

__global__ __launch_bounds__(NTHREADS, 1)
void linattn_kernel(const float* __restrict__ Qg,
                    const float* __restrict__ Kg,
                    const float* __restrict__ Vg,
                    const float* __restrict__ Mg,
                    float* __restrict__ Og)
{
    extern __shared__ float sm[];
    float* Qs = sm + OFF_Q;
    float* Ks = sm + OFF_K;
    float* Vs = sm + OFF_V;
    float* Ss = sm + OFF_S;

    const int tid  = threadIdx.x;
    const int warp = tid >> 5;          // warp == head index h
    const int lane = tid & 31;
    const int b    = blockIdx.y;
    const int q0   = blockIdx.x * TQ_;

    // Phase-1 micro-tile coords: qg in 0..3 (8 q-rows each), kg in 0..7 (4 k-cols each)
    const int qg = lane >> 3;
    const int kg = lane & 7;
    // Phase-2 micro-tile coords: qg2 in 0..3 (8 q-rows), dg in 0..7 (8 d-cols)
    const int qg2 = qg;
    const int dg  = kg;

    // ---- Load Q tile for all 8 heads, relu applied at store ----
    // 32 rows x 512 floats = 4096 float4 loads; tid+256*i -> (q, h, d4)
    #pragma unroll
    for (int i = 0; i < 16; i++) {
        int idx = tid + NTHREADS * i;
        int q   = idx >> 7;             // /128
        int rem = idx & 127;
        int h   = rem >> 4;
        int d4  = rem & 15;
        const float4 v = *reinterpret_cast<const float4*>(
            Qg + (((size_t)(b * H_ + h) * NQ_ + (q0 + q)) * D_ + d4 * 4));
        *reinterpret_cast<float4*>(&Qs[q * ST_ + h * D_ + d4 * 4]) = relu4(v);
    }

    // Persistent output accumulator: warp h owns O_h[32 x 64]; thread micro 8x8.
    float oacc[8][8];
    #pragma unroll
    for (int r = 0; r < 8; r++)
        #pragma unroll
        for (int c = 0; c < 8; c++) oacc[r][c] = 0.f;

    __syncthreads();

    for (int k0 = 0; k0 < NK_; k0 += TK_) {
        // ---- Load K (relu'd) and V tiles for all heads ----
        #pragma unroll
        for (int i = 0; i < 16; i++) {
            int idx = tid + NTHREADS * i;
            int k   = idx >> 7;
            int rem = idx & 127;
            int h   = rem >> 4;
            int d4  = rem & 15;
            size_t goff = (((size_t)(b * H_ + h) * NK_ + (k0 + k)) * D_ + d4 * 4);
            float4 kv = *reinterpret_cast<const float4*>(Kg + goff);
            float4 vv = *reinterpret_cast<const float4*>(Vg + goff);
            *reinterpret_cast<float4*>(&Ks[k * ST_ + h * D_ + d4 * 4]) = relu4(kv);
            *reinterpret_cast<float4*>(&Vs[k * ST_ + h * D_ + d4 * 4]) = vv;
        }
        __syncthreads();

        // ---- Phase 1: S_h[32x32] = reluQ_h[32x64] @ reluK_h[64x32]^T (h = warp) ----
        float sacc[8][4];
        #pragma unroll
        for (int r = 0; r < 8; r++)
            #pragma unroll
            for (int c = 0; c < 4; c++) sacc[r][c] = 0.f;

        const int hcol = warp * D_;
        #pragma unroll
        for (int d4 = 0; d4 < 16; d4++) {
            const int dcol = hcol + d4 * 4;
            float4 a[8], bb[4];
            #pragma unroll
            for (int r = 0; r < 8; r++)
                a[r] = *reinterpret_cast<const float4*>(&Qs[(qg + 4 * r) * ST_ + dcol]);
            #pragma unroll
            for (int c = 0; c < 4; c++)
                bb[c] = *reinterpret_cast<const float4*>(&Ks[(kg + 8 * c) * ST_ + dcol]);
            #pragma unroll
            for (int r = 0; r < 8; r++)
                #pragma unroll
                for (int c = 0; c < 4; c++) {
                    sacc[r][c] += a[r].x * bb[c].x;
                    sacc[r][c] += a[r].y * bb[c].y;
                    sacc[r][c] += a[r].z * bb[c].z;
                    sacc[r][c] += a[r].w * bb[c].w;
                }
        }

        // Store S_h to smem
        #pragma unroll
        for (int r = 0; r < 8; r++)
            #pragma unroll
            for (int c = 0; c < 4; c++)
                Ss[(warp * TQ_ + (qg + 4 * r)) * SST_ + (kg + 8 * c)] = sacc[r][c];
        __syncthreads();

        // ---- Normalize by head-sum, apply mask: P = S / (sum_h S) * mask ----
        // 1024 (q,k) pairs; each thread handles 4. Lane-consecutive k -> no conflicts.
        #pragma unroll
        for (int i = 0; i < 4; i++) {
            int idx = tid + NTHREADS * i;   // 0..1023
            int q = idx >> 5;
            int k = idx & 31;
            float s[H_];
            float denom = 0.f;
            #pragma unroll
            for (int hh = 0; hh < H_; hh++) {
                s[hh] = Ss[(hh * TQ_ + q) * SST_ + k];
                denom += s[hh];
            }
            const float m = Mg[(size_t)b * NQ_ * NK_ + (size_t)(q0 + q) * NK_ + (k0 + k)];
            const float inv = m / denom;    // reference has no epsilon; denom > 0 w.p. 1
            #pragma unroll
            for (int hh = 0; hh < H_; hh++)
                Ss[(hh * TQ_ + q) * SST_ + k] = s[hh] * inv;
        }
        __syncthreads();

        // ---- Phase 2: O_h += P_h[32x32] @ V_h[32x64] ----
        const float* Ph = &Ss[warp * TQ_ * SST_];
        #pragma unroll
        for (int k = 0; k < TK_; k++) {
            float p[8];
            #pragma unroll
            for (int r = 0; r < 8; r++) p[r] = Ph[(qg2 + 4 * r) * SST_ + k];
            const float4 v0 = *reinterpret_cast<const float4*>(&Vs[k * ST_ + hcol + dg * 4]);
            const float4 v1 = *reinterpret_cast<const float4*>(&Vs[k * ST_ + hcol + 32 + dg * 4]);
            #pragma unroll
            for (int r = 0; r < 8; r++) {
                oacc[r][0] += p[r] * v0.x;
                oacc[r][1] += p[r] * v0.y;
                oacc[r][2] += p[r] * v0.z;
                oacc[r][3] += p[r] * v0.w;
                oacc[r][4] += p[r] * v1.x;
                oacc[r][5] += p[r] * v1.y;
                oacc[r][6] += p[r] * v1.z;
                oacc[r][7] += p[r] * v1.w;
            }
        }
        __syncthreads();    // K/V/S buffers reused next iteration
    }

    // ---- Epilogue: out = O + raw query ----
    #pragma unroll
    for (int r = 0; r < 8; r++) {
        const int q = q0 + qg2 + 4 * r;
        const size_t base = ((size_t)(b * H_ + warp) * NQ_ + q) * D_;
        const float4 qa = *reinterpret_cast<const float4*>(Qg + base + dg * 4);
        const float4 qb = *reinterpret_cast<const float4*>(Qg + base + 32 + dg * 4);
        float4 o0, o1;
        o0.x = oacc[r][0] + qa.x;  o0.y = oacc[r][1] + qa.y;
        o0.z = oacc[r][2] + qa.z;  o0.w = oacc[r][3] + qa.w;
        o1.x = oacc[r][4] + qb.x;  o1.y = oacc[r][5] + qb.y;
        o1.z = oacc[r][6] + qb.z;  o1.w = oacc[r][7] + qb.w;
        *reinterpret_cast<float4*>(Og + base + dg * 4) = o0;
        *reinterpret_cast<float4*>(Og + base + 32 + dg * 4) = o1;
    }
}

extern "C" void kernel_launch(void* const* d_in, const int* in_sizes, int n_in,
                              void* d_out, int out_size)
{
    (void)in_sizes; (void)n_in; (void)out_size;
    const float* Qg = (const float*)d_in[0];
    const float* Kg = (const float*)d_in[1];
    const float* Vg = (const float*)d_in[2];
    const float* Mg = (const float*)d_in[3];
    float* Og = (float*)d_out;

    // Opt into >48KB dynamic smem (idempotent; executes immediately, not captured).
    static bool attr_set = false;
    if (!attr_set) {
        cudaFuncSetAttribute(linattn_kernel,
                             cudaFuncAttributeMaxDynamicSharedMemorySize,
                             (int)SMEM_BYTES);
        attr_set = true;
    }

    dim3 grid(NQ_ / TQ_, B_);   // (64, 2) = 128 CTAs
    dim3 block(NTHREADS);
    linattn_kernel<<<grid, block, SMEM_BYTES>>>(Qg, Kg, Vg, Mg, Og);
}

// round 2
// speedup vs baseline: 1.0015x; 1.0015x over previous
#include <cuda_runtime.h>
#include <cstdint>
#include <cstdio>

// Problem constants (fixed shapes).
namespace {
constexpr int B_  = 2;
constexpr int H_  = 8;
constexpr int NQ_ = 2048;
constexpr int NK_ = 2048;
constexpr int D_  = 64;
constexpr int HD_ = H_ * D_;        // 512
constexpr int TQ_ = 32;             // q-tile rows per CTA
constexpr int TK_ = 32;             // k-tile rows per iteration
constexpr int ST_ = HD_ + 4;        // smem row stride (floats), pad 4 -> conflict-free
constexpr int SST_ = TK_ + 1;       // S-tile row stride (33)
constexpr int NTHREADS = 256;       // 8 warps = 8 heads

// Shared memory layout (float offsets)
constexpr int OFF_Q = 0;                        // relu(Q) tile  [TQ][ST]
constexpr int OFF_K = OFF_Q + TQ_ * ST_;        // relu(K) tile  [TK][ST]
constexpr int OFF_V = OFF_K + TK_ * ST_;        // V tile        [TK][ST]
constexpr int OFF_S = OFF_V + TK_ * ST_;        // S/P tiles     [H][TQ][SST]
constexpr int SMEM_FLOATS = OFF_S + H_ * TQ_ * SST_;
constexpr size_t SMEM_BYTES = (size_t)SMEM_FLOATS * sizeof(float);  // 231,936 B
}

__device__ __forceinline__ float4 relu4(float4 v) {
    v.x = fmaxf(v.x, 0.f); v.y = fmaxf(v.y, 0.f);
    v.z = fmaxf(v.z, 0.f); v.w = fmaxf(v.w, 0.f);
    return v;
}

__global__ __launch_bounds__(NTHREADS, 1)
void linattn_kernel(const float* __restrict__ Qg,
                    const float* __restrict__ Kg,
                    const float* __restrict__ Vg,
                    const float* __restrict__ Mg,
                    float* __restrict__ Og)
{
    extern __shared__ float sm[];
    float* Qs = sm + OFF_Q;
    float* Ks = sm + OFF_K;
    float* Vs = sm + OFF_V;
    float* Ss = sm + OFF_S;

    const int tid  = threadIdx.x;
    const int warp = tid >> 5;          // warp == head index h
    const int lane = tid & 31;
    const int b    = blockIdx.y;
    const int q0   = blockIdx.x * TQ_;

    // Phase-1 micro-tile coords: qg in 0..3 (8 q-rows each), kg in 0..7 (4 k-cols each)
    const int qg = lane >> 3;
    const int kg = lane & 7;
    // Phase-2 micro-tile coords: qg2 in 0..3 (8 q-rows), dg in 0..7 (8 d-cols)
    const int qg2 = qg;
    const int dg  = kg;

    // ---- Load Q tile for all 8 heads, relu applied at store ----
    // 32 rows x 512 floats = 4096 float4 loads; tid+256*i -> (q, h, d4)
    #pragma unroll
    for (int i = 0; i < 16; i++) {
        int idx = tid + NTHREADS * i;
        int q   = idx >> 7;             // /128
        int rem = idx & 127;
        int h   = rem >> 4;
        int d4  = rem & 15;
        const float4 v = *reinterpret_cast<const float4*>(
            Qg + (((size_t)(b * H_ + h) * NQ_ + (q0 + q)) * D_ + d4 * 4));
        *reinterpret_cast<float4*>(&Qs[q * ST_ + h * D_ + d4 * 4]) = relu4(v);
    }

    // Persistent output accumulator: warp h owns O_h[32 x 64]; thread micro 8x8.
    float oacc[8][8];
    #pragma unroll
    for (int r = 0; r < 8; r++)
        #pragma unroll
        for (int c = 0; c < 8; c++) oacc[r][c] = 0.f;

    __syncthreads();

    for (int k0 = 0; k0 < NK_; k0 += TK_) {
        // ---- Load K (relu'd) and V tiles for all heads ----
        #pragma unroll
        for (int i = 0; i < 16; i++) {
            int idx = tid + NTHREADS * i;
            int k   = idx >> 7;
            int rem = idx & 127;
            int h   = rem >> 4;
            int d4  = rem & 15;
            size_t goff = (((size_t)(b * H_ + h) * NK_ + (k0 + k)) * D_ + d4 * 4);
            float4 kv = *reinterpret_cast<const float4*>(Kg + goff);
            float4 vv = *reinterpret_cast<const float4*>(Vg + goff);
            *reinterpret_cast<float4*>(&Ks[k * ST_ + h * D_ + d4 * 4]) = relu4(kv);
            *reinterpret_cast<float4*>(&Vs[k * ST_ + h * D_ + d4 * 4]) = vv;
        }
        __syncthreads();

        // ---- Phase 1: S_h[32x32] = reluQ_h[32x64] @ reluK_h[64x32]^T (h = warp) ----
        float sacc[8][4];
        #pragma unroll
        for (int r = 0; r < 8; r++)
            #pragma unroll
            for (int c = 0; c < 4; c++) sacc[r][c] = 0.f;

        const int hcol = warp * D_;
        #pragma unroll
        for (int d4 = 0; d4 < 16; d4++) {
            const int dcol = hcol + d4 * 4;
            float4 a[8], bb[4];
            #pragma unroll
            for (int r = 0; r < 8; r++)
                a[r] = *reinterpret_cast<const float4*>(&Qs[(qg + 4 * r) * ST_ + dcol]);
            #pragma unroll
            for (int c = 0; c < 4; c++)
                bb[c] = *reinterpret_cast<const float4*>(&Ks[(kg + 8 * c) * ST_ + dcol]);
            #pragma unroll
            for (int r = 0; r < 8; r++)
                #pragma unroll
                for (int c = 0; c < 4; c++) {
                    sacc[r][c] += a[r].x * bb[c].x;
                    sacc[r][c] += a[r].y * bb[c].y;
                    sacc[r][c] += a[r].z * bb[c].z;
                    sacc[r][c] += a[r].w * bb[c].w;
                }
        }

        // Store S_h to smem
        #pragma unroll
        for (int r = 0; r < 8; r++)
            #pragma unroll
            for (int c = 0; c < 4; c++)
                Ss[(warp * TQ_ + (qg + 4 * r)) * SST_ + (kg + 8 * c)] = sacc[r][c];
        __syncthreads();

        // ---- Normalize by head-sum, apply mask: P = S / (sum_h S) * mask ----
        // 1024 (q,k) pairs; each thread handles 4. Lane-consecutive k -> no conflicts.
        #pragma unroll
        for (int i = 0; i < 4; i++) {
            int idx = tid + NTHREADS * i;   // 0..1023
            int q = idx >> 5;
            int k = idx & 31;
            float s[H_];
            float denom = 0.f;
            #pragma unroll
            for (int hh = 0; hh < H_; hh++) {
                s[hh] = Ss[(hh * TQ_ + q) * SST_ + k];
                denom += s[hh];
            }
            const float m = Mg[(size_t)b * NQ_ * NK_ + (size_t)(q0 + q) * NK_ + (k0 + k)];
            const float inv = m / denom;    // reference has no epsilon; denom > 0 w.p. 1
            #pragma unroll
            for (int hh = 0; hh < H_; hh++)
                Ss[(hh * TQ_ + q) * SST_ + k] = s[hh] * inv;
        }
        __syncthreads();

        // ---- Phase 2: O_h += P_h[32x32] @ V_h[32x64] ----
        const float* Ph = &Ss[warp * TQ_ * SST_];
        #pragma unroll
        for (int k = 0; k < TK_; k++) {
            float p[8];
            #pragma unroll
            for (int r = 0; r < 8; r++) p[r] = Ph[(qg2 + 4 * r) * SST_ + k];
            const float4 v0 = *reinterpret_cast<const float4*>(&Vs[k * ST_ + hcol + dg * 4]);
            const float4 v1 = *reinterpret_cast<const float4*>(&Vs[k * ST_ + hcol + 32 + dg * 4]);
            #pragma unroll
            for (int r = 0; r < 8; r++) {
                oacc[r][0] += p[r] * v0.x;
                oacc[r][1] += p[r] * v0.y;
                oacc[r][2] += p[r] * v0.z;
                oacc[r][3] += p[r] * v0.w;
                oacc[r][4] += p[r] * v1.x;
                oacc[r][5] += p[r] * v1.y;
                oacc[r][6] += p[r] * v1.z;
                oacc[r][7] += p[r] * v1.w;
            }
        }
        __syncthreads();    // K/V/S buffers reused next iteration
    }

    // ---- Epilogue: out = O + raw query ----
    #pragma unroll
    for (int r = 0; r < 8; r++) {
        const int q = q0 + qg2 + 4 * r;
        const size_t base = ((size_t)(b * H_ + warp) * NQ_ + q) * D_;
        const float4 qa = *reinterpret_cast<const float4*>(Qg + base + dg * 4);
        const float4 qb = *reinterpret_cast<const float4*>(Qg + base + 32 + dg * 4);
        float4 o0, o1;
        o0.x = oacc[r][0] + qa.x;  o0.y = oacc[r][1] + qa.y;
        o0.z = oacc[r][2] + qa.z;  o0.w = oacc[r][3] + qa.w;
        o1.x = oacc[r][4] + qb.x;  o1.y = oacc[r][5] + qb.y;
        o1.z = oacc[r][6] + qb.z;  o1.w = oacc[r][7] + qb.w;
        *reinterpret_cast<float4*>(Og + base + dg * 4) = o0;
        *reinterpret_cast<float4*>(Og + base + 32 + dg * 4) = o1;
    }
}

extern "C" void kernel_launch(void* const* d_in, const int* in_sizes, int n_in,
                              void* d_out, int out_size)
{
    (void)in_sizes; (void)n_in; (void)out_size;
    const float* Qg = (const float*)d_in[0];
    const float* Kg = (const float*)d_in[1];
    const float* Vg = (const float*)d_in[2];
    const float* Mg = (const float*)d_in[3];
    float* Og = (float*)d_out;

    // Opt into >48KB dynamic smem (idempotent; executes immediately, not captured).
    static bool attr_set = false;
    if (!attr_set) {
        cudaFuncSetAttribute(linattn_kernel,
                             cudaFuncAttributeMaxDynamicSharedMemorySize,
                             (int)SMEM_BYTES);
        attr_set = true;
    }

    dim3 grid(NQ_ / TQ_, B_);   // (64, 2) = 128 CTAs
    dim3 block(NTHREADS);
    linattn_kernel<<<grid, block, SMEM_BYTES>>>(Qg, Kg, Vg, Mg, Og);
}

// round 5
// speedup vs baseline: 2.0642x; 2.0611x over previous
#include <cuda_runtime.h>
#include <cstdint>

namespace {
constexpr int B_  = 2;
constexpr int H_  = 8;
constexpr int NQ_ = 2048;
constexpr int NK_ = 2048;
constexpr int D_  = 64;
constexpr int TQ_ = 32;
constexpr int TK_ = 32;
constexpr int NTHREADS = 256;        // 8 warps = 8 heads

// Q/K/V tiles: 32 rows x 512 floats, row stride 516 (pad 4).
//   bank(r,col) = (4r + col) & 31  -> fragment accesses conflict-free, NO aliasing.
// S tiles: 8 heads x 32 rows x 32, row stride 36; overlays the K region
//   (K is fully register-resident after phase-1 fragment loads + barrier).
constexpr int QK_STRIDE = 516;
constexpr int TILE_SZ   = 32 * QK_STRIDE;       // 16512 floats
constexpr int OFF_Q   = 0;
constexpr int OFF_K   = TILE_SZ;                // 16512
constexpr int OFF_V   = 2 * TILE_SZ;            // 33024
constexpr int OFF_S   = OFF_K;                  // S overlays K (9216 <= 16512)
constexpr int S_HSTR  = 32 * 36;                // 1152 floats per head
constexpr int SMEM_FLOATS = 3 * TILE_SZ;        // 49536
constexpr size_t SMEM_BYTES = (size_t)SMEM_FLOATS * sizeof(float);  // 198144
}

__device__ __forceinline__ int qk_addr(int row, int col) { return row * QK_STRIDE + col; }
__device__ __forceinline__ int s_addr (int h, int row, int k) { return h * S_HSTR + row * 36 + k; }

__device__ __forceinline__ uint32_t tf32r(float f) {
    uint32_t r; asm("cvt.rna.tf32.f32 %0, %1;" : "=r"(r) : "f"(f)); return r;
}
__device__ __forceinline__ float tf32f(float f) { return __uint_as_float(tf32r(f)); }
__device__ __forceinline__ float tf32relu(float f) { return __uint_as_float(tf32r(fmaxf(f, 0.f))); }

// D += A(16x8,row) * B(8x8,col)   tf32 inputs, f32 accumulate
__device__ __forceinline__ void mma_tf32(float* d, const uint32_t* a, const uint32_t* b) {
    asm volatile(
        "mma.sync.aligned.m16n8k8.row.col.f32.tf32.tf32.f32 "
        "{%0,%1,%2,%3}, {%4,%5,%6,%7}, {%8,%9}, {%0,%1,%2,%3};"
        : "+f"(d[0]), "+f"(d[1]), "+f"(d[2]), "+f"(d[3])
        : "r"(a[0]), "r"(a[1]), "r"(a[2]), "r"(a[3]), "r"(b[0]), "r"(b[1]));
}

__global__ __launch_bounds__(NTHREADS, 1)
void linattn_mma(const float* __restrict__ Qg, const float* __restrict__ Kg,
                 const float* __restrict__ Vg, const float* __restrict__ Mg,
                 float* __restrict__ Og)
{
    extern __shared__ float sm[];
    float* Qs = sm + OFF_Q;
    float* Ks = sm + OFF_K;
    float* Vs = sm + OFF_V;
    float* Ss = sm + OFF_S;

    const int tid  = threadIdx.x;
    const int warp = tid >> 5;          // warp == head h
    const int lane = tid & 31;
    const int g    = lane >> 2;         // group id 0..7
    const int c    = lane & 3;          // thread-in-group 0..3
    const int b    = blockIdx.y;
    const int q0   = blockIdx.x * TQ_;
    const int h    = warp;
    const int hcol = h * D_;

    // ---- Load Q tile (relu + tf32 at store) ----
    #pragma unroll
    for (int i = 0; i < 16; i++) {
        int idx = tid + NTHREADS * i;               // 4096 float4
        int q = idx >> 7, rem = idx & 127;
        int hh = rem >> 4, d4 = rem & 15;
        float4 v = *reinterpret_cast<const float4*>(
            Qg + (((size_t)(b * H_ + hh) * NQ_ + q0 + q) * D_ + d4 * 4));
        float4 t;
        t.x = tf32relu(v.x); t.y = tf32relu(v.y);
        t.z = tf32relu(v.z); t.w = tf32relu(v.w);
        *reinterpret_cast<float4*>(&Qs[qk_addr(q, hh * D_ + d4 * 4)]) = t;
    }

    // Persistent O accumulator fragments: [mtile][ntile][4]
    float oacc[2][8][4];
    #pragma unroll
    for (int m = 0; m < 2; m++)
        #pragma unroll
        for (int n = 0; n < 8; n++)
            #pragma unroll
            for (int r = 0; r < 4; r++) oacc[m][n][r] = 0.f;

    __syncthreads();

    for (int k0 = 0; k0 < NK_; k0 += TK_) {
        // ---- Load K (relu+tf32) and V (tf32) tiles ----
        #pragma unroll
        for (int i = 0; i < 16; i++) {
            int idx = tid + NTHREADS * i;
            int k = idx >> 7, rem = idx & 127;
            int hh = rem >> 4, d4 = rem & 15;
            size_t go = ((size_t)(b * H_ + hh) * NK_ + k0 + k) * D_ + d4 * 4;
            float4 kv = *reinterpret_cast<const float4*>(Kg + go);
            float4 vv = *reinterpret_cast<const float4*>(Vg + go);
            float4 tk, tv;
            tk.x = tf32relu(kv.x); tk.y = tf32relu(kv.y);
            tk.z = tf32relu(kv.z); tk.w = tf32relu(kv.w);
            tv.x = tf32f(vv.x);    tv.y = tf32f(vv.y);
            tv.z = tf32f(vv.z);    tv.w = tf32f(vv.w);
            *reinterpret_cast<float4*>(&Ks[qk_addr(k, hh * D_ + d4 * 4)]) = tk;
            *reinterpret_cast<float4*>(&Vs[qk_addr(k, hh * D_ + d4 * 4)]) = tv;
        }
        __syncthreads();

        // ---- Phase 1: S_h[32x32] = Q_h[32x64] @ K_h[32x64]^T ----
        float sacc[2][4][4];
        #pragma unroll
        for (int m = 0; m < 2; m++)
            #pragma unroll
            for (int n = 0; n < 4; n++)
                #pragma unroll
                for (int r = 0; r < 4; r++) sacc[m][n][r] = 0.f;

        #pragma unroll
        for (int t = 0; t < 8; t++) {               // k-dim (d) tiles of 8
            const int colb = hcol + 8 * t + c;
            uint32_t a[2][4], bb[4][2];
            #pragma unroll
            for (int m = 0; m < 2; m++) {
                a[m][0] = __float_as_uint(Qs[qk_addr(16 * m + g,     colb)]);
                a[m][1] = __float_as_uint(Qs[qk_addr(16 * m + g + 8, colb)]);
                a[m][2] = __float_as_uint(Qs[qk_addr(16 * m + g,     colb + 4)]);
                a[m][3] = __float_as_uint(Qs[qk_addr(16 * m + g + 8, colb + 4)]);
            }
            #pragma unroll
            for (int n = 0; n < 4; n++) {
                bb[n][0] = __float_as_uint(Ks[qk_addr(8 * n + g, colb)]);
                bb[n][1] = __float_as_uint(Ks[qk_addr(8 * n + g, colb + 4)]);
            }
            #pragma unroll
            for (int m = 0; m < 2; m++)
                #pragma unroll
                for (int n = 0; n < 4; n++)
                    mma_tf32(sacc[m][n], a[m], bb[n]);
        }

        // All warps done reading K before S overwrites the K region.
        __syncthreads();

        // Store S fragments (float2: cols 2c,2c+1 contiguous)
        #pragma unroll
        for (int m = 0; m < 2; m++)
            #pragma unroll
            for (int n = 0; n < 4; n++) {
                *reinterpret_cast<float2*>(&Ss[s_addr(h, 16 * m + g,     8 * n + 2 * c)]) =
                    make_float2(sacc[m][n][0], sacc[m][n][1]);
                *reinterpret_cast<float2*>(&Ss[s_addr(h, 16 * m + g + 8, 8 * n + 2 * c)]) =
                    make_float2(sacc[m][n][2], sacc[m][n][3]);
            }
        __syncthreads();

        // ---- Normalize: P = S * mask / sum_h(S), tf32-rounded at store ----
        #pragma unroll
        for (int j = 0; j < 4; j++) {
            int idx = tid + NTHREADS * j;           // 0..1023
            int q = idx >> 5, k = idx & 31;
            float s[H_], den = 0.f;
            #pragma unroll
            for (int hh = 0; hh < H_; hh++) { s[hh] = Ss[s_addr(hh, q, k)]; den += s[hh]; }
            const float mval = Mg[(size_t)b * NQ_ * NK_ + (size_t)(q0 + q) * NK_ + k0 + k];
            const float inv = mval / den;
            #pragma unroll
            for (int hh = 0; hh < H_; hh++)
                Ss[s_addr(hh, q, k)] = tf32f(s[hh] * inv);
        }
        __syncthreads();

        // ---- Phase 2: O_h += P_h[32x32] @ V_h[32x64] ----
        #pragma unroll
        for (int t = 0; t < 4; t++) {               // k-dim (k-rows) tiles of 8
            uint32_t a[2][4], bb[8][2];
            #pragma unroll
            for (int m = 0; m < 2; m++) {
                a[m][0] = __float_as_uint(Ss[s_addr(h, 16 * m + g,     8 * t + c)]);
                a[m][1] = __float_as_uint(Ss[s_addr(h, 16 * m + g + 8, 8 * t + c)]);
                a[m][2] = __float_as_uint(Ss[s_addr(h, 16 * m + g,     8 * t + c + 4)]);
                a[m][3] = __float_as_uint(Ss[s_addr(h, 16 * m + g + 8, 8 * t + c + 4)]);
            }
            #pragma unroll
            for (int n = 0; n < 8; n++) {
                bb[n][0] = __float_as_uint(Vs[qk_addr(8 * t + c,     hcol + 8 * n + g)]);
                bb[n][1] = __float_as_uint(Vs[qk_addr(8 * t + c + 4, hcol + 8 * n + g)]);
            }
            #pragma unroll
            for (int m = 0; m < 2; m++)
                #pragma unroll
                for (int n = 0; n < 8; n++)
                    mma_tf32(oacc[m][n], a[m], bb[n]);
        }
        __syncthreads();    // S (=K region) and V reused next iteration
    }

    // ---- Epilogue: out = O + raw query ----
    #pragma unroll
    for (int m = 0; m < 2; m++)
        #pragma unroll
        for (int n = 0; n < 8; n++) {
            const int q1 = q0 + 16 * m + g;
            const size_t base = ((size_t)(b * H_ + h) * NQ_ + q1) * D_ + 8 * n + 2 * c;
            const float2 r0 = *reinterpret_cast<const float2*>(Qg + base);
            *reinterpret_cast<float2*>(Og + base) =
                make_float2(oacc[m][n][0] + r0.x, oacc[m][n][1] + r0.y);
            const size_t base2 = base + 8 * (size_t)D_;   // row q1+8
            const float2 r1 = *reinterpret_cast<const float2*>(Qg + base2);
            *reinterpret_cast<float2*>(Og + base2) =
                make_float2(oacc[m][n][2] + r1.x, oacc[m][n][3] + r1.y);
        }
}

extern "C" void kernel_launch(void* const* d_in, const int* in_sizes, int n_in,
                              void* d_out, int out_size)
{
    (void)in_sizes; (void)n_in; (void)out_size;
    const float* Qg = (const float*)d_in[0];
    const float* Kg = (const float*)d_in[1];
    const float* Vg = (const float*)d_in[2];
    const float* Mg = (const float*)d_in[3];
    float* Og = (float*)d_out;

    static bool attr_set = false;
    if (!attr_set) {
        cudaFuncSetAttribute(linattn_mma,
                             cudaFuncAttributeMaxDynamicSharedMemorySize,
                             (int)SMEM_BYTES);
        attr_set = true;
    }

    dim3 grid(NQ_ / TQ_, B_);   // (64, 2) = 128 CTAs, one wave
    linattn_mma<<<grid, NTHREADS, SMEM_BYTES>>>(Qg, Kg, Vg, Mg, Og);
}